// round 17
// baseline (speedup 1.0000x reference)
#include <cuda_runtime.h>
#include <cuda_bf16.h>
#include <cuda_fp16.h>
#include <cstdint>
#include <math.h>

#define HT   128
#define CC   256
#define FF   128
#define BB   4
#define NU   32
#define NOUT 2304
#define NG   1024
#define PIF  3.14159265358979323846f

typedef __nv_bfloat16 bf16;

// ---------------- scratch globals ----------------
__device__ __align__(16) bf16   g_Wgh[4 * NG * 32];
__device__ __align__(16) bf16   g_Wgl[4 * NG * 32];
__device__ __align__(16) float  g_bg[4 * NG];
__device__ __align__(16) float  g_Hc[128 * 32];
__device__ __align__(16) float  g_Wc[128 * 32];
__device__ __align__(16) float  g_Cc[32];
__device__ __align__(16) bf16   g_x4h[(size_t)16384 * 32];
__device__ __align__(16) bf16   g_x4l[(size_t)16384 * 32];
__device__ __align__(16) __half g_WpT16[(size_t)FF * CC];
// transposed ker: [h][chunk][g][w][c32]
__device__ __align__(16) __half g_kerT[(size_t)128 * 8 * 4 * 128 * 32];

__device__ __forceinline__ void split_bf(float v, bf16& hi, bf16& lo) {
    hi = __float2bfloat16(v);
    lo = __float2bfloat16(v - __bfloat162float(hi));
}
__device__ __forceinline__ void mma16816(float c[4], const uint32_t a[4], const uint32_t b[2]) {
    asm volatile(
        "mma.sync.aligned.m16n8k16.row.col.f32.bf16.bf16.f32 "
        "{%0,%1,%2,%3}, {%4,%5,%6,%7}, {%8,%9}, {%0,%1,%2,%3};"
        : "+f"(c[0]), "+f"(c[1]), "+f"(c[2]), "+f"(c[3])
        : "r"(a[0]), "r"(a[1]), "r"(a[2]), "r"(a[3]), "r"(b[0]), "r"(b[1]));
}
__device__ __forceinline__ void mma16816h(float c[4], const uint32_t a[4], const uint32_t b[2]) {
    asm volatile(
        "mma.sync.aligned.m16n8k16.row.col.f32.f16.f16.f32 "
        "{%0,%1,%2,%3}, {%4,%5,%6,%7}, {%8,%9}, {%0,%1,%2,%3};"
        : "+f"(c[0]), "+f"(c[1]), "+f"(c[2]), "+f"(c[3])
        : "r"(a[0]), "r"(a[1]), "r"(a[2]), "r"(a[3]), "r"(b[0]), "r"(b[1]));
}
__device__ __forceinline__ void ldsm_x4(uint32_t& r0, uint32_t& r1, uint32_t& r2, uint32_t& r3,
                                        uint32_t addr) {
    asm volatile("ldmatrix.sync.aligned.m8n8.x4.shared.b16 {%0,%1,%2,%3}, [%4];"
                 : "=r"(r0), "=r"(r1), "=r"(r2), "=r"(r3) : "r"(addr));
}
__device__ __forceinline__ int grp(int t, int par) { return (t == 0) ? 0 : (t == 2) ? 1 : (par ? 0 : 1); }

__device__ __forceinline__ void cp16(uint32_t dst, const void* src, int sz) {
    asm volatile("cp.async.cg.shared.global [%0], [%1], 16, %2;"
                 :: "r"(dst), "l"(src), "r"(sz));
}
#define CP_COMMIT() asm volatile("cp.async.commit_group;" ::: "memory")
#define CP_WAIT0()  asm volatile("cp.async.wait_group 0;" ::: "memory")

// ---------------------------------------------------------------------------
// prep (Wg part remapped: consecutive threads -> consecutive c, coalesced Wo)
// ---------------------------------------------------------------------------
__global__ __launch_bounds__(256) void prep_kernel(
    const float* __restrict__ Wo, const float* __restrict__ bo,
    const float* __restrict__ Wp,
    const float* __restrict__ W1, const float* __restrict__ b1)
{
    int idx = blockIdx.x * 256 + threadIdx.x;
    if (idx < 4 * NG * 32) {
        int par = idx >> 15, rem = idx & 32767;
        int k = rem >> 10;              // 0..31 (slow)
        int n = rem & 1023;             // fast -> consecutive c
        int g = n >> 8, c = n & 255, gr = g >> 1, gc = g & 1;
        int ph = par >> 1, pw = par & 1;
        float s = 0.0f;
        #pragma unroll
        for (int tr = 0; tr < 3; ++tr)
            #pragma unroll
            for (int tc = 0; tc < 3; ++tc)
                if (grp(tr, ph) == gr && grp(tc, pw) == gc)
                    s += Wo[(size_t)k * NOUT + (tr * 3 + tc) * 256 + c];
        bf16 hi, lo; split_bf(s, hi, lo);
        size_t o = (size_t)par * 32768 + (size_t)n * 32 + k;
        g_Wgh[o] = hi; g_Wgl[o] = lo;
    } else if ((idx -= 4 * NG * 32) < 4 * NG) {
        int par = idx >> 10, n = idx & 1023;
        int g = n >> 8, c = n & 255, gr = g >> 1, gc = g & 1;
        int ph = par >> 1, pw = par & 1;
        float s = 0.0f;
        #pragma unroll
        for (int tr = 0; tr < 3; ++tr)
            #pragma unroll
            for (int tc = 0; tc < 3; ++tc)
                if (grp(tr, ph) == gr && grp(tc, pw) == gc)
                    s += bo[(tr * 3 + tc) * 256 + c];
        g_bg[idx] = s;
    } else if ((idx -= 4 * NG) < FF * CC) {
        int n = idx >> 8, k = idx & 255;
        g_WpT16[idx] = __float2half(Wp[(size_t)k * FF + n]);
    } else if ((idx -= FF * CC) < 4096) {
        int h = idx >> 5, j = idx & 31;
        float s = 0.0f;
        for (int i = 0; i < 25; ++i) {
            float f = 1.0f + (float)i * (1.0f / 24.0f);
            s += cosf(PIF * (2.0f * h * (1.0f / 127.0f) + 1.0f) * f) * W1[i * 32 + j];
        }
        g_Hc[idx] = s;
    } else if ((idx -= 4096) < 4096) {
        int w = idx >> 5, j = idx & 31;
        float s = 0.0f;
        for (int i = 0; i < 25; ++i) {
            float f = 1.0f + (float)i * (1.0f / 24.0f);
            s += cosf(PIF * (2.0f * w * (1.0f / 127.0f) + 1.0f) * f) * W1[(25 + i) * 32 + j];
        }
        g_Wc[idx] = s;
    } else if ((idx -= 4096) < 32) {
        int j = idx;
        float s = b1[j];
        for (int i = 0; i < 50; ++i) {
            float f = 1.0f + (float)(i % 25) * (1.0f / 24.0f);
            s += cosf(PIF * 5.0f * f) * W1[(50 + i) * 32 + j];
        }
        for (int i = 100; i < 118; ++i) s -= W1[i * 32 + j];
        g_Cc[j] = s;
    }
}

// ---------------------------------------------------------------------------
// mlp (16 px/CTA, grid 1024)
// ---------------------------------------------------------------------------
__global__ __launch_bounds__(256) void mlp_kernel(
    const float* __restrict__ W2, const float* __restrict__ b2,
    const float* __restrict__ W3, const float* __restrict__ b3,
    const float* __restrict__ W4, const float* __restrict__ b4)
{
    __shared__ float xa[16][32];
    __shared__ float xb[16][32];
    const int tid = threadIdx.x;
    const int pix0 = blockIdx.x * 16;

    for (int o = tid; o < 512; o += 256) {
        int p = o >> 5, j = o & 31;
        int pix = pix0 + p, h = pix >> 7, w = pix & 127;
        xa[p][j] = fmaxf(g_Hc[h * 32 + j] + g_Wc[w * 32 + j] + g_Cc[j], 0.0f);
    }
    __syncthreads();
    for (int o = tid; o < 512; o += 256) {
        int p = o >> 5, j = o & 31;
        float s = b2[j];
        #pragma unroll
        for (int k = 0; k < NU; ++k) s += xa[p][k] * W2[k * NU + j];
        xb[p][j] = fmaxf(s, 0.0f);
    }
    __syncthreads();
    for (int o = tid; o < 512; o += 256) {
        int p = o >> 5, j = o & 31;
        float s = b3[j];
        #pragma unroll
        for (int k = 0; k < NU; ++k) s += xb[p][k] * W3[k * NU + j];
        xa[p][j] = fmaxf(s, 0.0f);
    }
    __syncthreads();
    for (int o = tid; o < 512; o += 256) {
        int p = o >> 5, j = o & 31;
        float s = b4[j];
        #pragma unroll
        for (int k = 0; k < NU; ++k) s += xa[p][k] * W4[k * NU + j];
        float v = fmaxf(s, 0.0f);
        int pix = pix0 + p, h = pix >> 7, w = pix & 127;
        int pp = (((h & 1) << 1) | (w & 1)) * 4096 + (h >> 1) * 64 + (w >> 1);
        bf16 hi, lo; split_bf(v, hi, lo);
        size_t o2 = (size_t)pp * 32 + j;
        g_x4h[o2] = hi; g_x4l[o2] = lo;
    }
}

// ---------------------------------------------------------------------------
// gemm1 v3: 64m x 128n tiles, grid (256, 8), 3 CTAs/SM, transposed epilogue.
// ---------------------------------------------------------------------------
__global__ __launch_bounds__(256, 3) void gemm1_kernel()
{
    __shared__ __align__(16) bf16 As[64 * 72];
    __shared__ __align__(16) bf16 Bs[128 * 72];

    const int tid = threadIdx.x;
    const int wid = tid >> 5, lane = tid & 31;
    const int gid = lane >> 2, tig = lane & 3;
    const int m0 = blockIdx.x * 64, n0g = blockIdx.y * 128;
    const int par = blockIdx.x >> 6;
    const int wm0 = (wid & 3) * 16, wn0 = (wid >> 2) * 64;

    const bf16* WgH = g_Wgh + (size_t)par * NG * 32;
    const bf16* WgL = g_Wgl + (size_t)par * NG * 32;

    {
        int r = tid >> 2, q = (tid & 3) * 8;   // 64 rows x 4
        *(uint4*)&As[r * 72 + q]      = *(const uint4*)&g_x4h[(size_t)(m0 + r) * 32 + q];
        *(uint4*)&As[r * 72 + 32 + q] = *(const uint4*)&g_x4l[(size_t)(m0 + r) * 32 + q];
    }
    for (int i = tid; i < 512; i += 256) {
        int r = i >> 2, q = (i & 3) * 8;
        *(uint4*)&Bs[r * 72 + q]      = *(const uint4*)&WgH[(size_t)(n0g + r) * 32 + q];
        *(uint4*)&Bs[r * 72 + 32 + q] = *(const uint4*)&WgL[(size_t)(n0g + r) * 32 + q];
    }
    __syncthreads();

    const uint32_t smA = (uint32_t)__cvta_generic_to_shared(As);
    const uint32_t smB = (uint32_t)__cvta_generic_to_shared(Bs);
    const int aRow = (lane & 7) + ((lane >> 3) & 1) * 8;
    const int aCol = ((lane >> 4) & 1) * 8;
    const int bRow = (lane & 7) + ((lane >> 4) & 1) * 8;
    const int bCol = ((lane >> 3) & 1) * 8;

    float c[8][4];
    #pragma unroll
    for (int j = 0; j < 8; ++j)
        #pragma unroll
        for (int e = 0; e < 4; ++e) c[j][e] = 0.0f;

    #pragma unroll
    for (int ks = 0; ks < 2; ++ks) {
        const int kb = ks * 16;
        uint32_t aH[4], aL[4];
        {
            uint32_t adr = smA + (uint32_t)((wm0 + aRow) * 72 + kb + aCol) * 2;
            ldsm_x4(aH[0], aH[1], aH[2], aH[3], adr);
            ldsm_x4(aL[0], aL[1], aL[2], aL[3], adr + 64);
        }
        #pragma unroll
        for (int nf = 0; nf < 8; nf += 2) {
            uint32_t b0H[2], b1H[2], b0L[2], b1L[2];
            uint32_t adr = smB + (uint32_t)((wn0 + nf * 8 + bRow) * 72 + kb + bCol) * 2;
            ldsm_x4(b0H[0], b0H[1], b1H[0], b1H[1], adr);
            ldsm_x4(b0L[0], b0L[1], b1L[0], b1L[1], adr + 64);
            mma16816(c[nf],     aH, b0H);
            mma16816(c[nf],     aH, b0L);
            mma16816(c[nf],     aL, b0H);
            mma16816(c[nf + 1], aH, b1H);
            mma16816(c[nf + 1], aH, b1L);
            mma16816(c[nf + 1], aL, b1H);
        }
    }

    // transposed epilogue -> g_kerT[((h*8+cc)*4+g)*4096 + w*32 + c32]
    const float* bgp = g_bg + par * NG;
    const int parh = par >> 1, parw = par & 1;
    #pragma unroll
    for (int half8 = 0; half8 < 2; ++half8) {
        int gm = m0 + wm0 + gid + half8 * 8;
        int rem = gm & 4095;
        int hh = ((rem >> 6) << 1) | parh;
        int ww = ((rem & 63) << 1) | parw;
        #pragma unroll
        for (int nf = 0; nf < 8; ++nf) {
            int gn = n0g + wn0 + nf * 8 + tig * 2;
            int g = gn >> 8, cg = gn & 255;
            int cc = cg >> 5, c32 = cg & 31;
            float bx = __ldg(&bgp[gn]), by = __ldg(&bgp[gn + 1]);
            float v0 = c[nf][half8 * 2 + 0] + bx;
            float v1 = c[nf][half8 * 2 + 1] + by;
            __half2 p = __floats2half2_rn(v0, v1);
            size_t addr = ((size_t)((hh * 8 + cc) * 4 + g) << 12) + ww * 32 + c32;
            *(__half2*)&g_kerT[addr] = p;
        }
    }
}

// ---------------------------------------------------------------------------
// fused gemm2 v9 (unchanged from R16): coalesced kerT loads, 4 CTAs/SM.
// ---------------------------------------------------------------------------
#define SM_AS    0
#define SM_BS    5120
#define BS_BYTES 10240
#define SM_XS    (SM_BS + 2 * BS_BYTES)
#define SM_TOT   (SM_XS + 19584)
#define XS_FLTS  2448
#define BSTR     40

__global__ __launch_bounds__(256, 4) void gemm2_fused9(
    const float* __restrict__ main_in,
    const float* __restrict__ bp, float* __restrict__ out)
{
    extern __shared__ __align__(16) uint8_t dsm[];
    __half* As = (__half*)(dsm + SM_AS);
    float*  Xs = (float*)(dsm + SM_XS);
    const uint32_t smb = (uint32_t)__cvta_generic_to_shared(dsm);

    const int tid = threadIdx.x;
    const int wid = tid >> 5, lane = tid & 31;
    const int gid = lane >> 2, tig = lane & 3;

    const int bx = blockIdx.x;
    const int whalf = bx & 1;
    const int b = (bx >> 1) & 3;
    const int h = bx >> 3;
    const int w0 = whalf * 64;
    const int c0 = whalf ? 31 : 0;

    const int wm = (wid & 3) * 16;
    const int wn = (wid >> 2) * 64;

    const int rA = (h - 1) >> 1, rB = (h + 1) >> 1;
    const bool vrA = h >= 1, vrB = h <= 126;

    const int awl = tid >> 2;
    const int w   = w0 + awl;
    const int ch0 = (tid & 3) * 8;
    const __half* kTb = g_kerT + ((size_t)(h * 8) << 14) + w * 32 + ch0;
    const int colA = ((w - 1) >> 1) - c0, colB = ((w + 1) >> 1) - c0;
    const bool vcA = w >= 1, vcB = w <= 126;

    const int aRow = (lane & 7) + ((lane >> 3) & 1) * 8;
    const int aCol = ((lane >> 4) & 1) * 8;
    const int bRow = (lane & 7) + ((lane >> 4) & 1) * 8;
    const int bCol = ((lane >> 3) & 1) * 8;

    float c[8][4];
    #pragma unroll
    for (int j = 0; j < 8; ++j)
        #pragma unroll
        for (int e = 0; e < 4; ++e) c[j][e] = 0.0f;

    auto stage = [&](int buf, int kc) {
        #pragma unroll
        for (int q = 0; q < 3; ++q) {
            int s = q * 256 + tid;
            if (s < 544) {
                int pos = s >> 3, qq = s & 7;
                int r = pos / 34, ci = pos - r * 34;
                int col = c0 + ci;
                bool ok = (r ? vrB : vrA) && (col < 64);
                int srow = r ? rB : rA; if (srow < 0) srow = 0;
                int scol = ok ? col : 0;
                const float* src = &main_in[(((size_t)b * 64 + srow) * 64 + scol) * CC + kc + qq * 4];
                uint32_t dst = smb + SM_XS + (uint32_t)(buf * XS_FLTS + pos * 36 + qq * 4) * 4;
                cp16(dst, src, ok ? 16 : 0);
            }
        }
        #pragma unroll
        for (int q = 0; q < 2; ++q) {
            int s = q * 256 + tid;
            int n = s >> 2, part = s & 3;
            const __half* src = g_WpT16 + (size_t)n * CC + kc + part * 8;
            uint32_t dst = smb + SM_BS + (uint32_t)(buf * BS_BYTES + (n * BSTR + part * 8) * 2);
            cp16(dst, src, 16);
        }
        CP_COMMIT();
    };

    stage(0, 0);
    CP_WAIT0();
    __syncthreads();

    for (int chunk = 0; chunk < 8; ++chunk) {
        const int cur = chunk & 1;
        const int kc  = chunk * 32;

        {
            const float* Xb = Xs + cur * XS_FLTS;
            const __half* kT = kTb + ((size_t)chunk << 14);
            float y[8];
            #pragma unroll
            for (int j = 0; j < 8; ++j) y[j] = 0.0f;
            #pragma unroll
            for (int g = 0; g < 4; ++g) {
                uint4 kv = *(const uint4*)&kT[(size_t)g << 12];
                int  rr  = g >> 1;
                int  cr  = (g & 1) ? colB : colA;
                bool ok  = (g & 1) ? vcB : vcA;
                float4 s0 = make_float4(0.f, 0.f, 0.f, 0.f), s1 = s0;
                if (ok) {
                    s0 = *(const float4*)&Xb[(rr * 34 + cr) * 36 + ch0];
                    s1 = *(const float4*)&Xb[(rr * 34 + cr) * 36 + ch0 + 4];
                }
                const __half2* kh = (const __half2*)&kv;
                float2 k01 = __half22float2(kh[0]);
                float2 k23 = __half22float2(kh[1]);
                float2 k45 = __half22float2(kh[2]);
                float2 k67 = __half22float2(kh[3]);
                y[0] += k01.x * s0.x; y[1] += k01.y * s0.y;
                y[2] += k23.x * s0.z; y[3] += k23.y * s0.w;
                y[4] += k45.x * s1.x; y[5] += k45.y * s1.y;
                y[6] += k67.x * s1.z; y[7] += k67.y * s1.w;
            }
            uint32_t hu[4];
            #pragma unroll
            for (int j2 = 0; j2 < 4; ++j2) {
                __half h0 = __float2half(y[j2 * 2]);
                __half h1 = __float2half(y[j2 * 2 + 1]);
                hu[j2] = (uint32_t)__half_as_ushort(h0) | ((uint32_t)__half_as_ushort(h1) << 16);
            }
            *(uint4*)&As[awl * BSTR + ch0] = make_uint4(hu[0], hu[1], hu[2], hu[3]);
        }
        __syncthreads();

        if (chunk < 7) stage(cur ^ 1, kc + 32);
        {
            const uint32_t smAa = smb + SM_AS;
            const uint32_t smBb = smb + SM_BS + (uint32_t)(cur * BS_BYTES);
            #pragma unroll
            for (int ks2 = 0; ks2 < 2; ++ks2) {
                const int kb = ks2 * 16;
                uint32_t a[4];
                {
                    uint32_t adr = smAa + (uint32_t)((wm + aRow) * BSTR + kb + aCol) * 2;
                    ldsm_x4(a[0], a[1], a[2], a[3], adr);
                }
                #pragma unroll
                for (int nf = 0; nf < 8; nf += 2) {
                    uint32_t b0[2], b1[2];
                    uint32_t adr = smBb + (uint32_t)((wn + nf * 8 + bRow) * BSTR + kb + bCol) * 2;
                    ldsm_x4(b0[0], b0[1], b1[0], b1[1], adr);
                    mma16816h(c[nf],     a, b0);
                    mma16816h(c[nf + 1], a, b1);
                }
            }
        }
        CP_WAIT0();
        __syncthreads();
    }

    const int gm = b * 16384 + h * 128 + w0 + wm + gid;
    #pragma unroll
    for (int nf = 0; nf < 8; ++nf) {
        int gn = wn + nf * 8 + tig * 2;
        float bx2 = __ldg(&bp[gn]), by2 = __ldg(&bp[gn + 1]);
        float2 v0 = { c[nf][0] + bx2, c[nf][1] + by2 };
        float2 v1 = { c[nf][2] + bx2, c[nf][3] + by2 };
        *(float2*)&out[(size_t)gm * FF + gn]       = v0;
        *(float2*)&out[(size_t)(gm + 8) * FF + gn] = v1;
    }
}

// ---------------------------------------------------------------------------
extern "C" void kernel_launch(void* const* d_in, const int* in_sizes, int n_in,
                              void* d_out, int out_size)
{
    const float* main_in = (const float*)d_in[0];
    const float* W1 = (const float*)d_in[2];
    const float* b1 = (const float*)d_in[3];
    const float* W2 = (const float*)d_in[4];
    const float* b2 = (const float*)d_in[5];
    const float* W3 = (const float*)d_in[6];
    const float* b3 = (const float*)d_in[7];
    const float* W4 = (const float*)d_in[8];
    const float* b4 = (const float*)d_in[9];
    const float* Wo = (const float*)d_in[10];
    const float* bo = (const float*)d_in[11];
    const float* Wp = (const float*)d_in[12];
    const float* bp = (const float*)d_in[13];
    float* out = (float*)d_out;

    cudaFuncSetAttribute(gemm2_fused9, cudaFuncAttributeMaxDynamicSharedMemorySize, SM_TOT);

    const int prep_elems = 4 * NG * 32 + 4 * NG + FF * CC + 4096 + 4096 + 32;
    prep_kernel<<<(prep_elems + 255) / 256, 256>>>(Wo, bo, Wp, W1, b1);
    mlp_kernel<<<1024, 256>>>(W2, b2, W3, b3, W4, b4);
    gemm1_kernel<<<dim3(256, 8), 256>>>();
    gemm2_fused9<<<1024, 256, SM_TOT>>>(main_in, bp, out);
}